// round 13
// baseline (speedup 1.0000x reference)
#include <cuda_runtime.h>
#include <cstdint>

#define NIMG 8
#define AN   16384
#define CN   21
#define NCLS 20
#define TOPK 100
#define NB   564            // buckets: (score_bits>>16) - 0x3D4C, scores in (0.05, 1)
#define BBASE 0x3D4Cu
#define THR_PROB 0.05f
#define THR_NMS  0.45f
#define CAP   8192          // per-(n,c) candidate capacity (actual ~4800, sigma ~42)
#define CAP2  2048          // per-chunk capacity
#define CHUNK 1536
#define NT    512           // k_rest block size

// -------- device scratch (no allocations allowed) --------
__device__ float4   g_boxes [NIMG * AN];
__device__ uint64_t g_cands [NIMG * NCLS * CAP];   // key = score_bits<<14 | (16383-anchor)
__device__ uint64_t g_sorted[NIMG * NCLS * CAP];   // bucket-descending scatter of g_cands
__device__ int      g_cnt   [NIMG * NCLS];          // push cursors; reset by k_rest
__device__ uint32_t g_hist  [NIMG * NCLS * 576];    // bucket histogram; reset by k_rest
__device__ float    g_rows  [NIMG * NCLS * TOPK * 6];
__device__ int      g_counts[NIMG * NCLS];
__device__ int      g_done  [NIMG];                 // per-image NMS completion counters

// ---------------- stage 1: softmax + decode + candidate push + global histogram ----------------
__global__ void __launch_bounds__(256) k_prep(const float* __restrict__ cls,
                                              const float* __restrict__ reg,
                                              const float* __restrict__ anc) {
    __shared__ float tile[8][672];   // 21 KB: per-warp staging of 32 anchors x 21 logits
    const unsigned FULL = 0xFFFFFFFFu;
    const int tid  = threadIdx.x;
    const int lane = tid & 31;
    const int wid  = tid >> 5;
    int t = blockIdx.x * blockDim.x + tid;           // grid exact: NIMG*AN threads
    int a = t & (AN - 1);
    int n = t >> 14;

    // coalesced float4 staging: 672 floats = 168 float4 per warp
    {
        const float4* src = (const float4*)(cls + (size_t)(t - lane) * CN);
        float4* dst = (float4*)tile[wid];
        #pragma unroll
        for (int i = 0; i < 5; i++) dst[lane + 32 * i] = src[lane + 32 * i];
        if (lane < 8) dst[lane + 160] = src[lane + 160];
        __syncwarp();
    }

    float x[CN];
    #pragma unroll
    for (int i = 0; i < CN; i++) x[i] = tile[wid][lane * CN + i];

    float mx = x[0];
    #pragma unroll
    for (int i = 1; i < CN; i++) mx = fmaxf(mx, x[i]);
    float e[CN];
    float sum = 0.f;
    #pragma unroll
    for (int i = 0; i < CN; i++) { e[i] = expf(x[i] - mx); sum += e[i]; }

    // one correctly-rounded reciprocal, then multiplies (vs 20 fdivs): scores shift by
    // <=1 ulp which cannot change any NMS-relevant decision and is far inside the
    // 1e-3 tolerance for stored scores.
    float inv = __fdiv_rn(1.0f, sum);

    // pass 1: probabilities + per-class ballots; lane c-1 keeps ballot of class c
    unsigned myBal = 0;
    #pragma unroll
    for (int c = 1; c < CN; c++) {
        float p = e[c] * inv;
        e[c] = p;
        unsigned b = __ballot_sync(FULL, p > THR_PROB);
        if (lane == c - 1) myBal = b;
    }
    // single warp-wide atomic: lane c updates class-c counter (spread addrs, one latency)
    int basePos = 0;
    if (lane < NCLS) basePos = atomicAdd(&g_cnt[n * NCLS + lane], __popc(myBal));

    // pass 2: positions + key stores + bucket histogram
    #pragma unroll
    for (int c = 1; c < CN; c++) {
        unsigned b = __shfl_sync(FULL, myBal, c - 1);
        int pos    = __shfl_sync(FULL, basePos, c - 1);
        if ((b >> lane) & 1) {
            int my = pos + __popc(b & ((1u << lane) - 1));
            uint32_t bits = __float_as_uint(e[c]);
            int nc = n * NCLS + (c - 1);
            if (my < CAP) {
                g_cands[(size_t)nc * CAP + my] =
                    ((uint64_t)bits << 14) | (uint64_t)(16383 - a);
                atomicAdd(&g_hist[nc * 576 + ((bits >> 16) - BBASE)], 1u);
            }
        }
    }

    float4 l   = ((const float4*)reg)[t];
    float4 an4 = ((const float4*)anc)[a];
    float cx = an4.x + l.x * 0.1f * an4.z;
    float cy = an4.y + l.y * 0.1f * an4.w;
    float w  = an4.z * expf(l.z * 0.2f);
    float h  = an4.w * expf(l.w * 0.2f);
    float hx = w * 0.5f, hy = h * 0.5f;
    float x1 = fminf(fmaxf(cx - hx, 0.f), 1.f);
    float y1 = fminf(fmaxf(cy - hy, 0.f), 1.f);
    float x2 = fminf(fmaxf(cx + hx, 0.f), 1.f);
    float y2 = fminf(fmaxf(cy + hy, 0.f), 1.f);
    g_boxes[t] = make_float4(x1, y1, x2, y2);
}

// IoU check with pre-hoisted areas; exact same op order as reference (IoU is symmetric:
// fmax/fmin/add are commutative, so operand order does not affect bits)
__device__ __forceinline__ bool iou_gt2(float4 p, float aP, float4 q, float aQ) {
    float ltx = fmaxf(p.x, q.x), lty = fmaxf(p.y, q.y);
    float rbx = fminf(p.z, q.z), rby = fminf(p.w, q.w);
    float iw = fmaxf(rbx - ltx, 0.f), ih = fmaxf(rby - lty, 0.f);
    float inter = iw * ih;
    float uni = aP + aQ - inter;
    float iou = (uni > 0.f) ? __fdiv_rn(inter, uni) : 0.f;
    return iou > THR_NMS;
}

// adaptive-width register bitonic sort, descending: width = ceil_pow2(L) <= 32.
// Zero padding sinks to the tail under descending order. W is warp-uniform.
__device__ __forceinline__ void bucket_sort_desc(uint64_t* seg, int L, int lane) {
    uint32_t W = 2;
    while ((int)W < L) W <<= 1;
    uint64_t v = (lane < L) ? seg[lane] : 0ull;
    for (uint32_t k = 2; k <= W; k <<= 1)
        for (uint32_t j = k >> 1; j > 0; j >>= 1) {
            uint64_t o = __shfl_xor_sync(0xFFFFFFFFu, v, j);
            bool keepMin = (((uint32_t)lane & j) == 0) == (((uint32_t)lane & k) != 0);
            uint64_t mn = v < o ? v : o;
            uint64_t mx = v < o ? o : v;
            v = keepMin ? mn : mx;
        }
    if (lane < L) seg[lane] = v;
}

// ---------------- stage 2+3 fused: NMS then (cc==0 blocks) per-image top-100 ----------------
// dynamic smem layout (bytes), NMS phase:
//   s_cbox   [CAP2] float4   @ 0       (32768)
//   s_selbox [TOPK] float4   @ 32768   (1600)
//   keys2    [CAP2] u64      @ 34368   (16384) -> 50752
//   s_cA     [CAP2] float    @ 50752   (8192)  -> 58944
//   s_selA   [TOPK] float    @ 58944   (400)   -> 59344
//   hist     [577] u32       @ 59344   (2308)  -> 61652
//   sufc     [577] u32       @ 61652   (2308)  -> 63960
//   cur      [576] u32       @ 63960   (2304)  -> 66264
// topk phase reuses: kb[2000] u64 @ 0, tkeys[2048] u64 @ 34368, hist, sufc
#define SMEM_NMS 66304

__global__ void __launch_bounds__(NT) k_rest(float* __restrict__ out) {
    extern __shared__ uint8_t dyn[];
    float4*   s_cbox   = (float4*)(dyn);
    float4*   s_selbox = (float4*)(dyn + 32768);
    uint64_t* keys2    = (uint64_t*)(dyn + 34368);
    float*    s_cA     = (float*)(dyn + 50752);
    float*    s_selA   = (float*)(dyn + 58944);
    uint32_t* hist     = (uint32_t*)(dyn + 59344);
    uint32_t* sufc     = (uint32_t*)(dyn + 61652);
    uint32_t* cur      = (uint32_t*)(dyn + 63960);

    __shared__ uint32_t s_mask[32];           // intra-window kill masks
    __shared__ uint32_t s_supb;               // suppressed-by-selected bitmask
    __shared__ int s_blo, s_selcnt;
    __shared__ int s_cnts[NCLS];
    __shared__ int s_bcut, s_m2;

    const unsigned FULL = 0xFFFFFFFFu;
    const int tid  = threadIdx.x;
    const int lane = tid & 31;
    const int wid  = tid >> 5;
    const int n    = blockIdx.x / NCLS;
    const int cc   = blockIdx.x % NCLS;
    const int nc   = n * NCLS + cc;
    const uint64_t* glist = g_cands + (size_t)nc * CAP;
    uint64_t*       gsort = g_sorted + (size_t)nc * CAP;
    const float4*   boxN  = g_boxes + (size_t)n * AN;
    float* rowBase = g_rows + (size_t)nc * TOPK * 6;

    // load per-class histogram from global (built by k_prep)
    for (int b = tid; b < 576; b += NT) { hist[b] = g_hist[nc * 576 + b]; cur[b] = 0; }
    if (tid == 0) s_selcnt = 0;
    if (tid < 32) s_mask[tid] = 0;
    if (tid == 0) s_supb = 0;
    __syncthreads();

    // suffix sums (warp 0): sufc[b] = #cands in buckets >= b
    if (tid < 32) {
        int hi = 576 - 18 * lane;
        int lo = hi - 18;
        uint32_t sum = 0;
        #pragma unroll
        for (int b = 0; b < 18; b++) sum += hist[lo + b];
        uint32_t pre = sum;
        #pragma unroll
        for (int d = 1; d < 32; d <<= 1) {
            uint32_t v = __shfl_up_sync(FULL, pre, d);
            if (lane >= d) pre += v;
        }
        uint32_t run = pre - sum;
        for (int b = hi - 1; b >= lo; b--) { run += hist[b]; sufc[b] = run; }
        if (lane == 0) sufc[576] = 0;
    }
    __syncthreads();

    int cnt = (int)sufc[0];
    if (cnt > CAP) cnt = CAP;

    // ---- scatter ONCE into bucket-descending global order ----
    // position of key in bucket b: sufc[b+1] + cur[b]++  (absolute in gsort)
    for (int i = tid; i < cnt; i += NT) {
        uint64_t key = glist[i];
        int b = (int)(uint32_t)(key >> 30) - (int)BBASE;
        uint32_t pos = sufc[b + 1] + atomicAdd(&cur[b], 1u);
        gsort[pos] = key;
    }
    __syncthreads();

    int b_hi = NB - 1;
    while (true) {
        const uint32_t base = sufc[b_hi + 1];    // consumed so far (uniform)
        if (tid == 0) {
            uint32_t target = base + CHUNK;
            int blo = 0;
            if (sufc[0] >= target) {
                int lo2 = 0, hi2 = b_hi;
                while (lo2 < hi2) {              // largest b with sufc[b] >= target
                    int mid = (lo2 + hi2 + 1) >> 1;
                    if (sufc[mid] >= target) lo2 = mid; else hi2 = mid - 1;
                }
                blo = lo2;
            }
            while (blo < b_hi && sufc[blo] - base > CAP2) blo++;   // capacity guard
            s_blo = blo;
        }
        __syncthreads();
        const int blo = s_blo;
        const int M = (int)(sufc[blo] - base);   // chunk is bucket-aligned

        // contiguous copy of this chunk's keys into smem
        for (int i = tid; i < M; i += NT) keys2[i] = gsort[base + i];
        __syncthreads();

        // per-bucket sort: warp w handles buckets blo+w, blo+w+16, ...
        for (int b = blo + wid; b <= b_hi; b += 16) {
            int L = (int)hist[b];
            if (L <= 1) continue;
            int seg = (int)(sufc[b + 1] - base);
            if (L <= 32) {
                bucket_sort_desc(keys2 + seg, L, lane);
            } else {
                for (int ph = 0; ph < L; ph++) {
                    for (int i = 2 * lane + (ph & 1); i + 1 < L; i += 64) {
                        uint64_t a = keys2[seg + i], b2 = keys2[seg + i + 1];
                        if (a < b2) { keys2[seg + i] = b2; keys2[seg + i + 1] = a; }
                    }
                    __syncwarp();
                }
            }
        }
        __syncthreads();

        // chunk-wide box prefetch: one exposed gather, high MLP
        for (int i = tid; i < M; i += NT) {
            uint64_t key = keys2[i];
            float4 b4 = boxN[16383u - ((uint32_t)key & 0x3FFFu)];
            s_cbox[i] = b4;
            s_cA[i]   = (b4.z - b4.x) * (b4.w - b4.y);
        }
        __syncthreads();

        // ---- block-parallel batch-32 greedy: exact sequential-greedy semantics ----
        // invariant at window entry: s_mask[*] == 0, s_supb == 0 (zeroed by phase B)
        for (int bw = 0; bw < M && s_selcnt < TOPK; bw += 32) {
            const int m = min(32, M - bw);
            const int selcnt = s_selcnt;

            // phase A: suppression vs selected list (warp w strides selected idx by 16)
            {
                int ci = bw + ((lane < m) ? lane : 0);
                float4 myb = s_cbox[ci];
                float  myA = s_cA[ci];
                bool kill = (lane >= m);          // tail lanes count as suppressed
                if (lane < m) {
                    #pragma unroll 4
                    for (int j = wid; j < selcnt; j += 16)
                        kill |= iou_gt2(s_selbox[j], s_selA[j], myb, myA);
                }
                unsigned bal = __ballot_sync(FULL, kill);
                if (lane == 0 && bal) atomicOr(&s_supb, bal);
            }
            // phase A2: intra-window kill matrix, <=496 pairs, one per thread
            {
                int npair = m * (m - 1) / 2;
                if (tid < npair) {
                    int p = tid;
                    int i = (int)((sqrtf((float)(8 * p + 1)) - 1.0f) * 0.5f);
                    while ((i + 1) * i / 2 <= p) i++;
                    while (i * (i - 1) / 2 > p) i--;
                    int j = p - i * (i - 1) / 2;     // j < i
                    if (iou_gt2(s_cbox[bw + j], s_cA[bw + j],
                                s_cbox[bw + i], s_cA[bw + i]))
                        atomicOr(&s_mask[i], 1u << j);
                }
            }
            __syncthreads();

            // phase B: serial resolution (warp 0); zero masks for next window
            if (wid == 0) {
                unsigned mymask = s_mask[lane];
                unsigned alive = ~s_supb;
                s_mask[lane] = 0;                 // re-arm for next window
                if (lane == 0) s_supb = 0;
                unsigned selMask = 0;
                int space = TOPK - selcnt;
                while (alive && space > 0) {
                    int i = __ffs(alive) - 1;
                    selMask |= 1u << i;
                    space--;
                    unsigned kk = __ballot_sync(FULL, (mymask >> i) & 1u);
                    alive &= ~kk;
                    alive &= ~(1u << i);
                }
                bool selme = (selMask >> lane) & 1;
                int rank = __popc(selMask & ((1u << lane) - 1));
                if (selme) {
                    int slot = selcnt + rank;
                    float4 b4 = s_cbox[bw + lane];
                    s_selbox[slot] = b4;
                    s_selA[slot]   = s_cA[bw + lane];
                    float* r = rowBase + slot * 6;
                    r[0] = b4.x; r[1] = b4.y; r[2] = b4.z; r[3] = b4.w;
                    r[4] = __uint_as_float((uint32_t)(keys2[bw + lane] >> 14));
                    r[5] = (float)(cc + 1);
                }
                if (lane == 0) s_selcnt = selcnt + __popc(selMask);
            }
            __syncthreads();
        }

        if (s_selcnt >= TOPK || blo == 0) {
            if (tid == 0) { g_counts[nc] = s_selcnt; g_cnt[nc] = 0; }
            break;
        }
        b_hi = blo - 1;
    }

    // reset this class's global histogram for the next graph replay
    for (int b = tid; b < 576; b += NT) g_hist[nc * 576 + b] = 0;

    // ---- NMS done for this (n,cc): publish, then cc==0 blocks run per-image top-k ----
    __threadfence();
    __syncthreads();
    if (tid == 0) atomicAdd(&g_done[n], 1);
    if (cc != 0) return;

    if (tid == 0) {
        while (atomicAdd(&g_done[n], 0) < NCLS) { }
    }
    __syncthreads();
    __threadfence();

    // reuse dynamic smem for topk
    uint64_t* kb     = (uint64_t*)(dyn);           // 2000 keys (16000 B)
    uint64_t* tkeys  = (uint64_t*)(dyn + 34368);   // 2048 compacted (16384 B)
    uint32_t* hist_t = hist;
    uint32_t* sufc_t = sufc;

    if (tid < NCLS) s_cnts[tid] = g_counts[n * NCLS + tid];
    for (int i = tid; i < 577; i += NT) hist_t[i] = 0;
    __syncthreads();

    for (int e = tid; e < NCLS * TOPK; e += NT) {
        int c = e / TOPK, k = e % TOPK;
        uint64_t key = 0ull;
        if (k < s_cnts[c]) {
            uint32_t sb = __float_as_uint(
                g_rows[(((size_t)(n * NCLS + c)) * TOPK + k) * 6 + 4]);
            uint32_t flat = (uint32_t)((c + 1) * TOPK + k);
            key = ((uint64_t)sb << 32) | (uint64_t)(4095u - flat);
            atomicAdd(&hist_t[(sb >> 16) - BBASE], 1u);
        }
        kb[e] = key;
    }
    __syncthreads();

    if (tid < 32) {
        int hi = 576 - 18 * lane;
        int lo = hi - 18;
        uint32_t sum = 0;
        #pragma unroll
        for (int b = 0; b < 18; b++) sum += hist_t[lo + b];
        uint32_t pre = sum;
        #pragma unroll
        for (int d = 1; d < 32; d <<= 1) {
            uint32_t v = __shfl_up_sync(FULL, pre, d);
            if (lane >= d) pre += v;
        }
        uint32_t run = pre - sum;
        for (int b = hi - 1; b >= lo; b--) { run += hist_t[b]; sufc_t[b] = run; }
    }
    __syncthreads();

    if (tid == 0) {
        uint32_t total = sufc_t[0];
        uint32_t target = total < TOPK ? total : TOPK;
        int bcut = 576;
        if (target > 0) {
            int lo2 = 0, hi2 = 575;
            while (lo2 < hi2) {
                int mid = (lo2 + hi2 + 1) >> 1;
                if (sufc_t[mid] >= target) lo2 = mid; else hi2 = mid - 1;
            }
            bcut = lo2;
        }
        s_bcut = bcut;
        s_m2 = 0;
    }
    __syncthreads();
    const int bcut = s_bcut;

    for (int e = (tid >> 5) * 32; e < NCLS * TOPK; e += NT) {
        int i = e + lane;
        uint64_t key = (i < NCLS * TOPK) ? kb[i] : 0ull;
        bool sel = key != 0ull && ((int)(uint32_t)(key >> 48) - (int)BBASE) >= bcut;
        unsigned bal = __ballot_sync(FULL, sel);
        if (bal) {
            int pos = 0;
            if (lane == 0) pos = atomicAdd(&s_m2, __popc(bal));
            pos = __shfl_sync(FULL, pos, 0);
            if (sel) tkeys[pos + __popc(bal & ((1u << lane) - 1))] = key;
        }
    }
    __syncthreads();
    int M2 = s_m2;

    int P = 32;
    while (P < M2) P <<= 1;
    for (int i = M2 + tid; i < P; i += NT) tkeys[i] = 0ull;
    __syncthreads();
    for (int k = 2; k <= P; k <<= 1)
        for (int j = k >> 1; j > 0; j >>= 1) {
            for (int i = tid; i < (P >> 1); i += NT) {
                int pos = ((i & ~(j - 1)) << 1) | (i & (j - 1));
                int par = pos | j;
                uint64_t xv = tkeys[pos], yv = tkeys[par];
                bool desc = ((pos & k) == 0);
                if (desc ? (xv < yv) : (xv > yv)) { tkeys[pos] = yv; tkeys[par] = xv; }
            }
            __syncthreads();
        }

    if (tid < TOPK) {
        float* o = out + ((size_t)n * TOPK + tid) * 6;
        uint64_t key = (tid < M2) ? tkeys[tid] : 0ull;
        if (key != 0ull) {
            uint32_t flat = 4095u - (uint32_t)key;
            int c = (int)(flat / TOPK) - 1;
            int k = (int)(flat % TOPK);
            const float* r = g_rows + (((size_t)(n * NCLS + c)) * TOPK + k) * 6;
            #pragma unroll
            for (int j = 0; j < 6; j++) o[j] = r[j];
        } else {
            #pragma unroll
            for (int j = 0; j < 6; j++) o[j] = 0.f;
        }
    }

    __syncthreads();
    if (tid == 0) atomicExch(&g_done[n], 0);   // reset for next graph replay
}

extern "C" void kernel_launch(void* const* d_in, const int* in_sizes, int n_in,
                              void* d_out, int out_size) {
    (void)in_sizes; (void)n_in; (void)out_size;
    const float* cls = (const float*)d_in[0];
    const float* reg = (const float*)d_in[1];
    const float* anc = (const float*)d_in[2];
    float* out = (float*)d_out;

    cudaFuncSetAttribute(k_rest, cudaFuncAttributeMaxDynamicSharedMemorySize, SMEM_NMS);

    k_prep<<<(NIMG * AN) / 256, 256>>>(cls, reg, anc);
    k_rest<<<NIMG * NCLS, NT, SMEM_NMS>>>(out);
}

// round 14
// speedup vs baseline: 1.3630x; 1.3630x over previous
#include <cuda_runtime.h>
#include <cstdint>

#define NIMG 8
#define AN   16384
#define CN   21
#define NCLS 20
#define TOPK 100
#define NB   564            // buckets: (score_bits>>16) - 0x3D4C, scores in (0.05, 1)
#define BBASE 0x3D4Cu
#define THR_PROB 0.05f
#define THR_NMS  0.45f
#define CAP   8192          // per-(n,c) candidate capacity (actual ~4800, sigma ~42)
#define CAP2  1024          // per-chunk box-prefetch capacity
#define CHUNK 512
#define NT    512           // k_rest block size

// -------- device scratch (no allocations allowed) --------
__device__ float4   g_boxes [NIMG * AN];
__device__ uint64_t g_cands [NIMG * NCLS * CAP];   // key = score_bits<<14 | (16383-anchor)
__device__ int      g_cnt   [NIMG * NCLS];          // push cursors; reset by k_rest
__device__ uint32_t g_hist  [NIMG * NCLS * 576];    // bucket histogram; reset by k_rest
__device__ float    g_rows  [NIMG * NCLS * TOPK * 6];
__device__ int      g_counts[NIMG * NCLS];
__device__ int      g_done  [NIMG];                 // per-image NMS completion counters

// ---------------- stage 1: softmax + decode + candidate push + global histogram ----------------
__global__ void __launch_bounds__(256) k_prep(const float* __restrict__ cls,
                                              const float* __restrict__ reg,
                                              const float* __restrict__ anc) {
    __shared__ float tile[8][672];   // 21 KB: per-warp staging of 32 anchors x 21 logits
    const unsigned FULL = 0xFFFFFFFFu;
    const int tid  = threadIdx.x;
    const int lane = tid & 31;
    const int wid  = tid >> 5;
    int t = blockIdx.x * blockDim.x + tid;           // grid exact: NIMG*AN threads
    int a = t & (AN - 1);
    int n = t >> 14;

    // coalesced float4 staging: 672 floats = 168 float4 per warp
    {
        const float4* src = (const float4*)(cls + (size_t)(t - lane) * CN);
        float4* dst = (float4*)tile[wid];
        #pragma unroll
        for (int i = 0; i < 5; i++) dst[lane + 32 * i] = src[lane + 32 * i];
        if (lane < 8) dst[lane + 160] = src[lane + 160];
        __syncwarp();
    }

    float x[CN];
    #pragma unroll
    for (int i = 0; i < CN; i++) x[i] = tile[wid][lane * CN + i];

    float mx = x[0];
    #pragma unroll
    for (int i = 1; i < CN; i++) mx = fmaxf(mx, x[i]);
    float e[CN];
    float sum = 0.f;
    #pragma unroll
    for (int i = 0; i < CN; i++) { e[i] = expf(x[i] - mx); sum += e[i]; }

    // one correctly-rounded reciprocal, then multiplies (vs 20 fdivs): scores shift by
    // <=1 ulp which cannot change any NMS-relevant decision and is far inside the
    // 1e-3 tolerance for stored scores.
    float inv = __fdiv_rn(1.0f, sum);

    // pass 1: probabilities + per-class ballots; lane c-1 keeps ballot of class c
    unsigned myBal = 0;
    #pragma unroll
    for (int c = 1; c < CN; c++) {
        float p = e[c] * inv;
        e[c] = p;
        unsigned b = __ballot_sync(FULL, p > THR_PROB);
        if (lane == c - 1) myBal = b;
    }
    // single warp-wide atomic: lane c updates class-c counter (spread addrs, one latency)
    int basePos = 0;
    if (lane < NCLS) basePos = atomicAdd(&g_cnt[n * NCLS + lane], __popc(myBal));

    // pass 2: positions + key stores + bucket histogram
    #pragma unroll
    for (int c = 1; c < CN; c++) {
        unsigned b = __shfl_sync(FULL, myBal, c - 1);
        int pos    = __shfl_sync(FULL, basePos, c - 1);
        if ((b >> lane) & 1) {
            int my = pos + __popc(b & ((1u << lane) - 1));
            uint32_t bits = __float_as_uint(e[c]);
            int nc = n * NCLS + (c - 1);
            if (my < CAP) {
                g_cands[(size_t)nc * CAP + my] =
                    ((uint64_t)bits << 14) | (uint64_t)(16383 - a);
                atomicAdd(&g_hist[nc * 576 + ((bits >> 16) - BBASE)], 1u);
            }
        }
    }

    float4 l   = ((const float4*)reg)[t];
    float4 an4 = ((const float4*)anc)[a];
    float cx = an4.x + l.x * 0.1f * an4.z;
    float cy = an4.y + l.y * 0.1f * an4.w;
    float w  = an4.z * expf(l.z * 0.2f);
    float h  = an4.w * expf(l.w * 0.2f);
    float hx = w * 0.5f, hy = h * 0.5f;
    float x1 = fminf(fmaxf(cx - hx, 0.f), 1.f);
    float y1 = fminf(fmaxf(cy - hy, 0.f), 1.f);
    float x2 = fminf(fmaxf(cx + hx, 0.f), 1.f);
    float y2 = fminf(fmaxf(cy + hy, 0.f), 1.f);
    g_boxes[t] = make_float4(x1, y1, x2, y2);
}

// IoU check with pre-hoisted areas; exact same op order as reference (IoU is symmetric:
// fmax/fmin/add are commutative, so operand order does not affect bits)
__device__ __forceinline__ bool iou_gt2(float4 p, float aP, float4 q, float aQ) {
    float ltx = fmaxf(p.x, q.x), lty = fmaxf(p.y, q.y);
    float rbx = fminf(p.z, q.z), rby = fminf(p.w, q.w);
    float iw = fmaxf(rbx - ltx, 0.f), ih = fmaxf(rby - lty, 0.f);
    float inter = iw * ih;
    float uni = aP + aQ - inter;
    float iou = (uni > 0.f) ? __fdiv_rn(inter, uni) : 0.f;
    return iou > THR_NMS;
}

// adaptive-width register bitonic sort, descending: width = ceil_pow2(L) <= 32.
// Zero padding sinks to the tail under descending order. W is warp-uniform.
__device__ __forceinline__ void bucket_sort_desc(uint64_t* seg, int L, int lane) {
    uint32_t W = 2;
    while ((int)W < L) W <<= 1;
    uint64_t v = (lane < L) ? seg[lane] : 0ull;
    for (uint32_t k = 2; k <= W; k <<= 1)
        for (uint32_t j = k >> 1; j > 0; j >>= 1) {
            uint64_t o = __shfl_xor_sync(0xFFFFFFFFu, v, j);
            bool keepMin = (((uint32_t)lane & j) == 0) == (((uint32_t)lane & k) != 0);
            uint64_t mn = v < o ? v : o;
            uint64_t mx = v < o ? o : v;
            v = keepMin ? mn : mx;
        }
    if (lane < L) seg[lane] = v;
}

// ---------------- stage 2+3 fused: NMS then (cc==0 blocks) per-image top-100 ----------------
// dynamic smem layout (bytes), NMS phase:
//   keys_all [CAP ] u64      @ 0       (65536)  all candidates, bucket-descending
//   s_cbox   [CAP2] float4   @ 65536   (16384) -> 81920
//   s_cA     [CAP2] float    @ 81920   (4096)  -> 86016
//   s_selbox [TOPK] float4   @ 86016   (1600)  -> 87616
//   s_selA   [TOPK] float    @ 87616   (400)   -> 88016
//   hist     [577] u32       @ 88016   (2308)  -> 90324
//   sufc     [577] u32       @ 90324   (2308)  -> 92632
//   cur      [576] u32       @ 92632   (2304)  -> 94936
// topk phase reuses: kb[2000] u64 @ 0, tkeys[2048] u64 @ 16384, hist, sufc
#define SMEM_NMS 94976

__global__ void __launch_bounds__(NT) k_rest(float* __restrict__ out) {
    extern __shared__ uint8_t dyn[];
    uint64_t* keys_all = (uint64_t*)(dyn);
    float4*   s_cbox   = (float4*)(dyn + 65536);
    float*    s_cA     = (float*)(dyn + 81920);
    float4*   s_selbox = (float4*)(dyn + 86016);
    float*    s_selA   = (float*)(dyn + 87616);
    uint32_t* hist     = (uint32_t*)(dyn + 88016);
    uint32_t* sufc     = (uint32_t*)(dyn + 90324);
    uint32_t* cur      = (uint32_t*)(dyn + 92632);

    __shared__ uint32_t s_mask[32];           // intra-window kill masks
    __shared__ uint32_t s_supb;               // suppressed-by-selected bitmask
    __shared__ int s_blo, s_selcnt;
    __shared__ int s_cnts[NCLS];
    __shared__ int s_bcut, s_m2;

    const unsigned FULL = 0xFFFFFFFFu;
    const int tid  = threadIdx.x;
    const int lane = tid & 31;
    const int wid  = tid >> 5;
    const int n    = blockIdx.x / NCLS;
    const int cc   = blockIdx.x % NCLS;
    const int nc   = n * NCLS + cc;
    const uint64_t* glist = g_cands + (size_t)nc * CAP;
    const float4*   boxN  = g_boxes + (size_t)n * AN;
    float* rowBase = g_rows + (size_t)nc * TOPK * 6;

    // load per-class histogram from global (built by k_prep)
    for (int b = tid; b < 576; b += NT) { hist[b] = g_hist[nc * 576 + b]; cur[b] = 0; }
    if (tid == 0) s_selcnt = 0;
    if (tid < 32) s_mask[tid] = 0;
    if (tid == 0) s_supb = 0;
    __syncthreads();

    // suffix sums (warp 0): sufc[b] = #cands in buckets >= b
    if (tid < 32) {
        int hi = 576 - 18 * lane;
        int lo = hi - 18;
        uint32_t sum = 0;
        #pragma unroll
        for (int b = 0; b < 18; b++) sum += hist[lo + b];
        uint32_t pre = sum;
        #pragma unroll
        for (int d = 1; d < 32; d <<= 1) {
            uint32_t v = __shfl_up_sync(FULL, pre, d);
            if (lane >= d) pre += v;
        }
        uint32_t run = pre - sum;
        for (int b = hi - 1; b >= lo; b--) { run += hist[b]; sufc[b] = run; }
        if (lane == 0) sufc[576] = 0;
    }
    __syncthreads();

    int cnt = (int)sufc[0];
    if (cnt > CAP) cnt = CAP;

    // ---- scatter ONCE into bucket-descending order, all in smem ----
    // key of bucket b goes to absolute position sufc[b+1] + cur[b]++
    for (int i = tid; i < cnt; i += NT) {
        uint64_t key = glist[i];
        int b = (int)(uint32_t)(key >> 30) - (int)BBASE;
        uint32_t pos = sufc[b + 1] + atomicAdd(&cur[b], 1u);
        keys_all[pos] = key;
    }
    __syncthreads();

    int b_hi = NB - 1;
    while (true) {
        const uint32_t base = sufc[b_hi + 1];    // consumed so far (uniform)
        if (tid == 0) {
            uint32_t target = base + CHUNK;
            int blo = 0;
            if (sufc[0] >= target) {
                int lo2 = 0, hi2 = b_hi;
                while (lo2 < hi2) {              // largest b with sufc[b] >= target
                    int mid = (lo2 + hi2 + 1) >> 1;
                    if (sufc[mid] >= target) lo2 = mid; else hi2 = mid - 1;
                }
                blo = lo2;
            }
            while (blo < b_hi && sufc[blo] - base > CAP2) blo++;   // capacity guard
            s_blo = blo;
        }
        __syncthreads();
        const int blo = s_blo;
        const int M = (int)(sufc[blo] - base);   // chunk is bucket-aligned

        // per-bucket sort in place (absolute offsets): warp w -> buckets blo+w, +16, ...
        for (int b = blo + wid; b <= b_hi; b += 16) {
            int L = (int)hist[b];
            if (L <= 1) continue;
            uint64_t* seg = keys_all + sufc[b + 1];
            if (L <= 32) {
                bucket_sort_desc(seg, L, lane);
            } else {
                for (int ph = 0; ph < L; ph++) {
                    for (int i = 2 * lane + (ph & 1); i + 1 < L; i += 64) {
                        uint64_t a = seg[i], b2 = seg[i + 1];
                        if (a < b2) { seg[i] = b2; seg[i + 1] = a; }
                    }
                    __syncwarp();
                }
            }
        }
        __syncthreads();

        // chunk-wide box prefetch: one exposed gather, high MLP
        for (int i = tid; i < M; i += NT) {
            uint64_t key = keys_all[base + i];
            float4 b4 = boxN[16383u - ((uint32_t)key & 0x3FFFu)];
            s_cbox[i] = b4;
            s_cA[i]   = (b4.z - b4.x) * (b4.w - b4.y);
        }
        __syncthreads();

        // ---- block-parallel batch-32 greedy: exact sequential-greedy semantics ----
        // invariant at window entry: s_mask[*] == 0, s_supb == 0 (zeroed by phase B)
        for (int bw = 0; bw < M && s_selcnt < TOPK; bw += 32) {
            const int m = min(32, M - bw);
            const int selcnt = s_selcnt;

            // phase A: suppression vs selected list (warp w strides selected idx by 16)
            {
                int ci = bw + ((lane < m) ? lane : 0);
                float4 myb = s_cbox[ci];
                float  myA = s_cA[ci];
                bool kill = (lane >= m);          // tail lanes count as suppressed
                if (lane < m) {
                    #pragma unroll 4
                    for (int j = wid; j < selcnt; j += 16)
                        kill |= iou_gt2(s_selbox[j], s_selA[j], myb, myA);
                }
                unsigned bal = __ballot_sync(FULL, kill);
                if (lane == 0 && bal) atomicOr(&s_supb, bal);
            }
            // phase A2: intra-window kill matrix, <=496 pairs, one per thread
            {
                int npair = m * (m - 1) / 2;
                if (tid < npair) {
                    int p = tid;
                    int i = (int)((sqrtf((float)(8 * p + 1)) - 1.0f) * 0.5f);
                    while ((i + 1) * i / 2 <= p) i++;
                    while (i * (i - 1) / 2 > p) i--;
                    int j = p - i * (i - 1) / 2;     // j < i
                    if (iou_gt2(s_cbox[bw + j], s_cA[bw + j],
                                s_cbox[bw + i], s_cA[bw + i]))
                        atomicOr(&s_mask[i], 1u << j);
                }
            }
            __syncthreads();

            // phase B: serial resolution (warp 0); zero masks for next window
            if (wid == 0) {
                unsigned mymask = s_mask[lane];
                unsigned alive = ~s_supb;
                s_mask[lane] = 0;                 // re-arm for next window
                if (lane == 0) s_supb = 0;
                unsigned selMask = 0;
                int space = TOPK - selcnt;
                while (alive && space > 0) {
                    int i = __ffs(alive) - 1;
                    selMask |= 1u << i;
                    space--;
                    unsigned kk = __ballot_sync(FULL, (mymask >> i) & 1u);
                    alive &= ~kk;
                    alive &= ~(1u << i);
                }
                bool selme = (selMask >> lane) & 1;
                int rank = __popc(selMask & ((1u << lane) - 1));
                if (selme) {
                    int slot = selcnt + rank;
                    float4 b4 = s_cbox[bw + lane];
                    s_selbox[slot] = b4;
                    s_selA[slot]   = s_cA[bw + lane];
                    float* r = rowBase + slot * 6;
                    r[0] = b4.x; r[1] = b4.y; r[2] = b4.z; r[3] = b4.w;
                    r[4] = __uint_as_float((uint32_t)(keys_all[base + bw + lane] >> 14));
                    r[5] = (float)(cc + 1);
                }
                if (lane == 0) s_selcnt = selcnt + __popc(selMask);
            }
            __syncthreads();
        }

        if (s_selcnt >= TOPK || blo == 0) {
            if (tid == 0) { g_counts[nc] = s_selcnt; g_cnt[nc] = 0; }
            break;
        }
        b_hi = blo - 1;
    }

    // reset this class's global histogram for the next graph replay
    for (int b = tid; b < 576; b += NT) g_hist[nc * 576 + b] = 0;

    // ---- NMS done for this (n,cc): publish, then cc==0 blocks run per-image top-k ----
    __threadfence();
    __syncthreads();
    if (tid == 0) atomicAdd(&g_done[n], 1);
    if (cc != 0) return;

    if (tid == 0) {
        while (atomicAdd(&g_done[n], 0) < NCLS) { }
    }
    __syncthreads();
    __threadfence();

    // reuse dynamic smem for topk
    uint64_t* kb     = (uint64_t*)(dyn);           // 2000 keys (16000 B)
    uint64_t* tkeys  = (uint64_t*)(dyn + 16384);   // 2048 compacted (16384 B)
    uint32_t* hist_t = hist;
    uint32_t* sufc_t = sufc;

    if (tid < NCLS) s_cnts[tid] = g_counts[n * NCLS + tid];
    for (int i = tid; i < 577; i += NT) hist_t[i] = 0;
    __syncthreads();

    for (int e = tid; e < NCLS * TOPK; e += NT) {
        int c = e / TOPK, k = e % TOPK;
        uint64_t key = 0ull;
        if (k < s_cnts[c]) {
            uint32_t sb = __float_as_uint(
                g_rows[(((size_t)(n * NCLS + c)) * TOPK + k) * 6 + 4]);
            uint32_t flat = (uint32_t)((c + 1) * TOPK + k);
            key = ((uint64_t)sb << 32) | (uint64_t)(4095u - flat);
            atomicAdd(&hist_t[(sb >> 16) - BBASE], 1u);
        }
        kb[e] = key;
    }
    __syncthreads();

    if (tid < 32) {
        int hi = 576 - 18 * lane;
        int lo = hi - 18;
        uint32_t sum = 0;
        #pragma unroll
        for (int b = 0; b < 18; b++) sum += hist_t[lo + b];
        uint32_t pre = sum;
        #pragma unroll
        for (int d = 1; d < 32; d <<= 1) {
            uint32_t v = __shfl_up_sync(FULL, pre, d);
            if (lane >= d) pre += v;
        }
        uint32_t run = pre - sum;
        for (int b = hi - 1; b >= lo; b--) { run += hist_t[b]; sufc_t[b] = run; }
    }
    __syncthreads();

    if (tid == 0) {
        uint32_t total = sufc_t[0];
        uint32_t target = total < TOPK ? total : TOPK;
        int bcut = 576;
        if (target > 0) {
            int lo2 = 0, hi2 = 575;
            while (lo2 < hi2) {
                int mid = (lo2 + hi2 + 1) >> 1;
                if (sufc_t[mid] >= target) lo2 = mid; else hi2 = mid - 1;
            }
            bcut = lo2;
        }
        s_bcut = bcut;
        s_m2 = 0;
    }
    __syncthreads();
    const int bcut = s_bcut;

    for (int e = (tid >> 5) * 32; e < NCLS * TOPK; e += NT) {
        int i = e + lane;
        uint64_t key = (i < NCLS * TOPK) ? kb[i] : 0ull;
        bool sel = key != 0ull && ((int)(uint32_t)(key >> 48) - (int)BBASE) >= bcut;
        unsigned bal = __ballot_sync(FULL, sel);
        if (bal) {
            int pos = 0;
            if (lane == 0) pos = atomicAdd(&s_m2, __popc(bal));
            pos = __shfl_sync(FULL, pos, 0);
            if (sel) tkeys[pos + __popc(bal & ((1u << lane) - 1))] = key;
        }
    }
    __syncthreads();
    int M2 = s_m2;

    int P = 32;
    while (P < M2) P <<= 1;
    for (int i = M2 + tid; i < P; i += NT) tkeys[i] = 0ull;
    __syncthreads();
    for (int k = 2; k <= P; k <<= 1)
        for (int j = k >> 1; j > 0; j >>= 1) {
            for (int i = tid; i < (P >> 1); i += NT) {
                int pos = ((i & ~(j - 1)) << 1) | (i & (j - 1));
                int par = pos | j;
                uint64_t xv = tkeys[pos], yv = tkeys[par];
                bool desc = ((pos & k) == 0);
                if (desc ? (xv < yv) : (xv > yv)) { tkeys[pos] = yv; tkeys[par] = xv; }
            }
            __syncthreads();
        }

    if (tid < TOPK) {
        float* o = out + ((size_t)n * TOPK + tid) * 6;
        uint64_t key = (tid < M2) ? tkeys[tid] : 0ull;
        if (key != 0ull) {
            uint32_t flat = 4095u - (uint32_t)key;
            int c = (int)(flat / TOPK) - 1;
            int k = (int)(flat % TOPK);
            const float* r = g_rows + (((size_t)(n * NCLS + c)) * TOPK + k) * 6;
            #pragma unroll
            for (int j = 0; j < 6; j++) o[j] = r[j];
        } else {
            #pragma unroll
            for (int j = 0; j < 6; j++) o[j] = 0.f;
        }
    }

    __syncthreads();
    if (tid == 0) atomicExch(&g_done[n], 0);   // reset for next graph replay
}

extern "C" void kernel_launch(void* const* d_in, const int* in_sizes, int n_in,
                              void* d_out, int out_size) {
    (void)in_sizes; (void)n_in; (void)out_size;
    const float* cls = (const float*)d_in[0];
    const float* reg = (const float*)d_in[1];
    const float* anc = (const float*)d_in[2];
    float* out = (float*)d_out;

    cudaFuncSetAttribute(k_rest, cudaFuncAttributeMaxDynamicSharedMemorySize, SMEM_NMS);

    k_prep<<<(NIMG * AN) / 256, 256>>>(cls, reg, anc);
    k_rest<<<NIMG * NCLS, NT, SMEM_NMS>>>(out);
}